// round 16
// baseline (speedup 1.0000x reference)
#include <cuda_runtime.h>
#include <stddef.h>
#include <stdint.h>

// Problem constants (fixed shapes for this problem)
#define BB 2048      // batch
#define SS 128       // seq len
#define DD 1024      // model dim
#define EE 8         // num experts
#define HH 2048      // expert hidden (2*D)
#define NSTEPS 5
#define NCLS 10
#define LN_EPS 1e-5f

// ---------------- scratch (static device globals; no runtime allocation) ---------
__device__ float g_h[(size_t)BB * DD];       // current hidden state h  (8 MB)
__device__ float g_hidden[(size_t)BB * DD];  // router MLP hidden      (8 MB)
__device__ float g_z[(size_t)BB * HH];       // expert hidden          (16 MB)
__device__ float g_z2[(size_t)BB * DD];      // expert pre-LN output   (8 MB)
__device__ int   g_active[BB];
__device__ int   g_route[BB];                // chosen expert this step, or -1
__device__ int   g_cnt[EE];                  // per-expert routed count this step
__device__ int   g_list[EE * BB];            // per-expert sample index lists
__device__ int   g_alist[2][BB];             // active-sample lists (parity buffered)
__device__ int   g_acnt[2];                  // active counts

// ---------------- tf32 helpers ----------------------------------------------------
__device__ __forceinline__ uint32_t f2tf32(float x) {
    uint32_t y;
    asm("cvt.rna.tf32.f32 %0, %1;" : "=r"(y) : "f"(x));
    return y;
}
// split raw float into (hi, lo) tf32 pair, as uint bit patterns for mma
__device__ __forceinline__ void split_u(float v, uint32_t& hi, uint32_t& lo) {
    hi = f2tf32(v);
    lo = f2tf32(v - __uint_as_float(hi));
}
__device__ __forceinline__ void mma8(float* c, const uint32_t* a, const uint32_t* b) {
    asm volatile(
        "mma.sync.aligned.m16n8k8.row.col.f32.tf32.tf32.f32 "
        "{%0,%1,%2,%3}, {%4,%5,%6,%7}, {%8,%9}, {%0,%1,%2,%3};"
        : "+f"(c[0]), "+f"(c[1]), "+f"(c[2]), "+f"(c[3])
        : "r"(a[0]), "r"(a[1]), "r"(a[2]), "r"(a[3]), "r"(b[0]), "r"(b[1]));
}
// ---------------- cp.async helpers -------------------------------------------------
__device__ __forceinline__ void cp16(uint32_t dst, const void* src) {
    asm volatile("cp.async.cg.shared.global [%0], [%1], 16;" :: "r"(dst), "l"(src));
}
__device__ __forceinline__ void cp_commit() {
    asm volatile("cp.async.commit_group;");
}
template <int NN>
__device__ __forceinline__ void cp_wait() {
    asm volatile("cp.async.wait_group %0;" :: "n"(NN));
}

// ---------------- pooling: h[b,:] = mean over non-pad tokens of emb[ids] ---------
__global__ void k_pool(const int* __restrict__ ids, const float* __restrict__ emb) {
    const int b = blockIdx.x;
    const int t = threadIdx.x;          // 256 threads, each owns 4 consecutive dims
    float4 acc = make_float4(0.f, 0.f, 0.f, 0.f);
    int cnt = 0;
    const int* row = ids + (size_t)b * SS;
    for (int s = 0; s < SS; s++) {
        const int id = row[s];
        cnt += (id != 0);
        // emb row 0 (padding) is all zeros in the input, so unconditional add is exact
        const float4 v = *(const float4*)(emb + (size_t)id * DD + t * 4);
        acc.x += v.x; acc.y += v.y; acc.z += v.z; acc.w += v.w;
    }
    const float inv = 1.0f / (float)(cnt > 0 ? cnt : 1);
    float4 o = make_float4(acc.x * inv, acc.y * inv, acc.z * inv, acc.w * inv);
    *(float4*)(g_h + (size_t)b * DD + t * 4) = o;
    if (t == 0) {
        g_active[b] = 1;
        g_alist[0][b] = b;              // step-0 active list = identity
        if (b == 0) g_acnt[0] = BB;
    }
}

// ---------------- 3xTF32 tensor-core GEMM: C[M,N] = act(A[M,K] @ W[K,N] + bias) ---
// Block tile 128x64, BK=32, 256 threads = 8 warps laid out 4(M)x2(N), warp tile
// 32x32 via 2x4 m16n8k8 tf32 MMAs, 3 passes (hi*hi + hi*lo + lo*hi); tf32 split
// happens at fragment-load time so arithmetic is bit-identical to prior rounds.
// 3-stage cp.async pipeline: panels stream gmem->SMEM with no register staging;
// one cp.async.wait_group + one __syncthreads per 32-k panel.
// SMEM: A raw fp32 [stage][128][36] (banks (4g+tg)%32, conflict-free),
//       W raw fp32 k-major [stage][32][72] (banks (8tg+g)%32, conflict-free;
//       k-major so cp.async 16B chunks are contiguous in gmem AND smem).
// GATHER: rows come from list rl (count *cntp), early-exit past count.
template <bool GATHER, bool RELU, int N, int K>
__device__ __forceinline__ void gemm_tf32(const float* __restrict__ A,
                                          const float* __restrict__ W,
                                          const float* __restrict__ bias,
                                          float* __restrict__ Cout,
                                          const int* __restrict__ rl,
                                          const int* __restrict__ cntp) {
    constexpr int BM = 128, BN = 64, BK = 32, LDA = 36, LDW = 72, NSTG = 3;
    constexpr int P = K / BK;
    extern __shared__ float sm[];
    float* As = sm;                          // [NSTG][BM][LDA]
    float* Ws = sm + NSTG * BM * LDA;        // [NSTG][BK][LDW]

    const int m0 = blockIdx.y * BM;
    const int n0 = blockIdx.x * BN;
    int mcount = BB;
    if (GATHER) {
        mcount = *cntp;
        if (m0 >= mcount) return;
    }

    const int tid = threadIdx.x;
    // A loader: 4 chunks/thread: row = (tid>>3)+j*32, col = (tid&7)*4  (16B each)
    const int car = tid >> 3;                // 0..31
    const int cac = (tid & 7) * 4;
    const float* Agp[4];
#pragma unroll
    for (int j = 0; j < 4; j++) {
        const int mrow = m0 + car + j * 32;
        int rg;
        if (GATHER) rg = (mrow < mcount) ? rl[mrow] : 0;  // dummy row 0 (store guarded)
        else        rg = mrow;
        Agp[j] = A + (size_t)rg * K + cac;
    }
    // W loader: k-row = tid>>3, n-offset = (tid&7)*8 -> two 16B chunks
    const int wkr = tid >> 3;                // 0..31
    const int wn8 = (tid & 7) * 8;
    const float* Wgp = W + (size_t)wkr * N + n0 + wn8;

    const uint32_t sA = (uint32_t)__cvta_generic_to_shared(As);
    const uint32_t sW = (uint32_t)__cvta_generic_to_shared(Ws);

    const int warp = tid >> 5;
    const int lane = tid & 31;
    const int wm = (warp & 3) * 32;          // warp M offset
    const int wn = (warp >> 2) * 32;         // warp N offset
    const int g  = lane >> 2;                // groupID 0..7
    const int tg = lane & 3;                 // threadInGroup 0..3

    float acc[2][4][4];
#pragma unroll
    for (int mi = 0; mi < 2; mi++)
#pragma unroll
        for (int ni = 0; ni < 4; ni++)
#pragma unroll
            for (int q = 0; q < 4; q++) acc[mi][ni][q] = 0.f;

    // stage issue: async-copy panel p into slot p%NSTG, commit as one group
    auto issue = [&](int p) {
        const int st = p % NSTG;
        const int kb = p * BK;
#pragma unroll
        for (int j = 0; j < 4; j++)
            cp16(sA + (uint32_t)(((st * BM + car + j * 32) * LDA + cac) * 4),
                 Agp[j] + kb);
        cp16(sW + (uint32_t)(((st * BK + wkr) * LDW + wn8) * 4),
             Wgp + (size_t)kb * N);
        cp16(sW + (uint32_t)(((st * BK + wkr) * LDW + wn8 + 4) * 4),
             Wgp + (size_t)kb * N + 4);
        cp_commit();
    };

    issue(0);
    issue(1);

    for (int p = 0; p < P; p++) {
        if (p + 2 < P) cp_wait<1>(); else cp_wait<0>();
        __syncthreads();
        if (p + 2 < P) issue(p + 2);   // slot (p-1)%3: all warps past its compute

        const int st = p % NSTG;
        const float* Ap = As + st * BM * LDA;
        const float* Wp = Ws + st * BK * LDW;
#pragma unroll
        for (int ks = 0; ks < BK; ks += 8) {
            uint32_t ah[2][4], alr[2][4], bh[4][2], bl[4][2];
#pragma unroll
            for (int mi = 0; mi < 2; mi++) {
                const int r = wm + mi * 16 + g;
                split_u(Ap[r * LDA + ks + tg],           ah[mi][0], alr[mi][0]);
                split_u(Ap[(r + 8) * LDA + ks + tg],     ah[mi][1], alr[mi][1]);
                split_u(Ap[r * LDA + ks + tg + 4],       ah[mi][2], alr[mi][2]);
                split_u(Ap[(r + 8) * LDA + ks + tg + 4], ah[mi][3], alr[mi][3]);
            }
#pragma unroll
            for (int ni = 0; ni < 4; ni++) {
                const int c = wn + ni * 8 + g;
                split_u(Wp[(ks + tg) * LDW + c],     bh[ni][0], bl[ni][0]);
                split_u(Wp[(ks + tg + 4) * LDW + c], bh[ni][1], bl[ni][1]);
            }
#pragma unroll
            for (int mi = 0; mi < 2; mi++)
#pragma unroll
                for (int ni = 0; ni < 4; ni++) {
                    mma8(acc[mi][ni], ah[mi], bh[ni]);   // hi*hi
                    mma8(acc[mi][ni], ah[mi], bl[ni]);   // hi*lo
                    mma8(acc[mi][ni], alr[mi], bh[ni]);  // lo*hi
                }
        }
    }

    // epilogue: C frag c0..c3 = rows (g, g+8), cols (tg*2, tg*2+1)
#pragma unroll
    for (int mi = 0; mi < 2; mi++) {
#pragma unroll
        for (int half = 0; half < 2; half++) {
            const int lr = wm + mi * 16 + g + half * 8;
            int gr;
            if (GATHER) {
                if (m0 + lr >= mcount) continue;
                gr = rl[m0 + lr];
            } else {
                gr = m0 + lr;
            }
#pragma unroll
            for (int ni = 0; ni < 4; ni++) {
                const int c = wn + ni * 8 + tg * 2;
                const float2 bv = *(const float2*)(bias + n0 + c);
                float v0 = acc[mi][ni][half * 2 + 0] + bv.x;
                float v1 = acc[mi][ni][half * 2 + 1] + bv.y;
                if (RELU) { v0 = fmaxf(v0, 0.f); v1 = fmaxf(v1, 0.f); }
                *(float2*)(Cout + (size_t)gr * N + n0 + c) = make_float2(v0, v1);
            }
        }
    }
}

#define GEMM_SMEM ((3 * 128 * 36 + 3 * 32 * 72) * (int)sizeof(float))  // 82944 B

__global__ void __launch_bounds__(256, 2)
k_router1(const float* __restrict__ W, const float* __restrict__ bvec, int par) {
    gemm_tf32<true, true, DD, DD>(g_h, W, bvec, g_hidden, g_alist[par], &g_acnt[par]);
}
__global__ void __launch_bounds__(256, 2)
k_expert1(const float* __restrict__ W, const float* __restrict__ bvec) {
    const int e = blockIdx.z;
    gemm_tf32<true, true, HH, DD>(g_h, W + (size_t)e * DD * HH, bvec + (size_t)e * HH,
                                  g_z, g_list + e * BB, g_cnt + e);
}
__global__ void __launch_bounds__(256, 2)
k_expert2(const float* __restrict__ W, const float* __restrict__ bvec) {
    const int e = blockIdx.z;
    gemm_tf32<true, false, DD, HH>(g_z, W + (size_t)e * HH * DD, bvec + (size_t)e * DD,
                                   g_z2, g_list + e * BB, g_cnt + e);
}

// ---------------- reset per-step counters -----------------------------------------
__global__ void k_reset(int nextpar) {
    if (threadIdx.x < EE) g_cnt[threadIdx.x] = 0;
    if (threadIdx.x == 0) g_acnt[nextpar] = 0;
}

// ---------------- router head: logits (E+1) -> argmax -> routing bookkeeping ------
__global__ void k_router2(const float* __restrict__ W2, const float* __restrict__ b2,
                          int par) {
    const int b = blockIdx.x;
    const int tid = threadIdx.x;
    const float* hid = g_hidden + (size_t)b * DD;
    float acc[EE + 1];
#pragma unroll
    for (int j = 0; j <= EE; j++) acc[j] = 0.f;
    for (int k = tid; k < DD; k += 256) {
        const float hv = hid[k];
#pragma unroll
        for (int j = 0; j <= EE; j++) acc[j] += hv * W2[k * (EE + 1) + j];
    }
    __shared__ float red[EE + 1][272];
#pragma unroll
    for (int j = 0; j <= EE; j++) red[j][tid] = acc[j];
    __syncthreads();
    for (int off = 128; off > 0; off >>= 1) {
        if (tid < off) {
#pragma unroll
            for (int j = 0; j <= EE; j++) red[j][tid] += red[j][tid + off];
        }
        __syncthreads();
    }
    if (tid == 0) {
        float best = red[0][0] + b2[0];
        int act = 0;
#pragma unroll
        for (int j = 1; j <= EE; j++) {
            const float v = red[j][0] + b2[j];
            if (v > best) { best = v; act = j; }   // strict '>' == first-max (jnp.argmax)
        }
        const int a = g_active[b];
        int r = -1;
        if (a && act < EE) {
            r = act;
            const int p = atomicAdd(&g_cnt[act], 1);
            g_list[act * BB + p] = b;
            const int q = atomicAdd(&g_acnt[par ^ 1], 1);  // survivor -> next active list
            g_alist[par ^ 1][q] = b;
        }
        g_route[b] = r;
        g_active[b] = (a && act < EE) ? 1 : 0;
    }
}

// ---------------- LayerNorm + residual:  h += LN(z2)*g + beta  (routed samples) ---
__global__ void k_ln(const float* __restrict__ eg, const float* __restrict__ ebt) {
    const int b = blockIdx.x;
    const int e = g_route[b];
    if (e < 0) return;
    const int tid = threadIdx.x;
    const float* z2 = g_z2 + (size_t)b * DD;
    float x[4];
#pragma unroll
    for (int i = 0; i < 4; i++) x[i] = z2[tid + i * 256];

    __shared__ float rb[256];
    rb[tid] = x[0] + x[1] + x[2] + x[3];
    __syncthreads();
    for (int off = 128; off > 0; off >>= 1) {
        if (tid < off) rb[tid] += rb[tid + off];
        __syncthreads();
    }
    const float mean = rb[0] * (1.0f / DD);
    __syncthreads();
    float vs = 0.f;
#pragma unroll
    for (int i = 0; i < 4; i++) { const float d = x[i] - mean; vs += d * d; }
    rb[tid] = vs;
    __syncthreads();
    for (int off = 128; off > 0; off >>= 1) {
        if (tid < off) rb[tid] += rb[tid + off];
        __syncthreads();
    }
    const float inv = rsqrtf(rb[0] * (1.0f / DD) + LN_EPS);
#pragma unroll
    for (int i = 0; i < 4; i++) {
        const int d = tid + i * 256;
        g_h[(size_t)b * DD + d] +=
            (x[i] - mean) * inv * eg[(size_t)e * DD + d] + ebt[(size_t)e * DD + d];
    }
}

// ---------------- output head: out[b,:] = h[b] @ o_W + o_b  (C=10) ----------------
__global__ void k_head(const float* __restrict__ oW, const float* __restrict__ ob,
                       float* __restrict__ out) {
    const int b = blockIdx.x;
    const int tid = threadIdx.x;
    const float* h = g_h + (size_t)b * DD;
    float acc[NCLS];
#pragma unroll
    for (int c = 0; c < NCLS; c++) acc[c] = 0.f;
    for (int k = tid; k < DD; k += 256) {
        const float hv = h[k];
#pragma unroll
        for (int c = 0; c < NCLS; c++) acc[c] += hv * oW[k * NCLS + c];
    }
    __shared__ float red[NCLS][272];
#pragma unroll
    for (int c = 0; c < NCLS; c++) red[c][tid] = acc[c];
    __syncthreads();
    for (int off = 128; off > 0; off >>= 1) {
        if (tid < off) {
#pragma unroll
            for (int c = 0; c < NCLS; c++) red[c][tid] += red[c][tid + off];
        }
        __syncthreads();
    }
    if (tid < NCLS) out[(size_t)b * NCLS + tid] = red[tid][0] + ob[tid];
}

// ---------------- launch sequence -------------------------------------------------
extern "C" void kernel_launch(void* const* d_in, const int* in_sizes, int n_in,
                              void* d_out, int out_size) {
    (void)in_sizes; (void)n_in; (void)out_size;
    const int*   ids = (const int*)d_in[0];
    const float* emb = (const float*)d_in[1];
    const float* rW1 = (const float*)d_in[2];
    const float* rb1 = (const float*)d_in[3];
    const float* rW2 = (const float*)d_in[4];
    const float* rb2 = (const float*)d_in[5];
    const float* eW1 = (const float*)d_in[6];
    const float* eb1 = (const float*)d_in[7];
    const float* eW2 = (const float*)d_in[8];
    const float* eb2 = (const float*)d_in[9];
    const float* eg  = (const float*)d_in[10];
    const float* ebt = (const float*)d_in[11];
    const float* oW  = (const float*)d_in[12];
    const float* ob  = (const float*)d_in[13];
    float* out = (float*)d_out;

    // 81 KB dynamic SMEM per GEMM CTA (idempotent host-side attribute set)
    cudaFuncSetAttribute(k_router1, cudaFuncAttributeMaxDynamicSharedMemorySize, GEMM_SMEM);
    cudaFuncSetAttribute(k_expert1, cudaFuncAttributeMaxDynamicSharedMemorySize, GEMM_SMEM);
    cudaFuncSetAttribute(k_expert2, cudaFuncAttributeMaxDynamicSharedMemorySize, GEMM_SMEM);

    k_pool<<<BB, 256>>>(ids, emb);
    for (int s = 0; s < NSTEPS; s++) {
        const int par = s & 1;
        k_reset<<<1, 32>>>(par ^ 1);
        k_router1<<<dim3(DD / 64, BB / 128, 1), 256, GEMM_SMEM>>>(rW1, rb1, par);
        k_router2<<<BB, 256>>>(rW2, rb2, par);
        k_expert1<<<dim3(HH / 64, BB / 128, EE), 256, GEMM_SMEM>>>(eW1, eb1);
        k_expert2<<<dim3(DD / 64, BB / 128, EE), 256, GEMM_SMEM>>>(eW2, eb2);
        k_ln<<<BB, 256>>>(eg, ebt);
    }
    k_head<<<BB, 256>>>(oW, ob, out);
}